// round 2
// baseline (speedup 1.0000x reference)
#include <cuda_runtime.h>
#include <cstdint>

#define N_NODES 100000
#define N_EDGES 1600000
#define IN_F 256
#define OUT_F 128

// Scratch for h = x @ W + b  (51.2 MB). __device__ global: allowed (no cudaMalloc).
__device__ float g_h[(size_t)N_NODES * OUT_F];

// ---------------------------------------------------------------------------
// GEMM: h[M,128] = x[M,256] @ W[256,128] + bias
// BM=128, BN=128 (full N), BK=32, 256 threads, 8x8 microtile per thread.
// ---------------------------------------------------------------------------
__global__ __launch_bounds__(256) void gemm_kernel(
    const float* __restrict__ x,
    const float* __restrict__ W,
    const float* __restrict__ bias,
    float* __restrict__ h)
{
    __shared__ float As[32][128 + 4];  // transposed A tile, padded vs stride-128 conflicts
    __shared__ float Bs[32][128];

    const int tid = threadIdx.x;
    const int tx = tid & 15;        // 16 col-groups of 8
    const int ty = tid >> 4;        // 16 row-groups of 8
    const int block_row = blockIdx.x * 128;

    float acc[8][8];
#pragma unroll
    for (int i = 0; i < 8; i++)
#pragma unroll
        for (int j = 0; j < 8; j++) acc[i][j] = 0.0f;

    for (int k0 = 0; k0 < IN_F; k0 += 32) {
        // Load A tile (128 rows x 32 k) transposed into As[k][row]
#pragma unroll
        for (int l = 0; l < 4; l++) {
            int idx = tid + l * 256;          // 0..1023
            int ar  = idx >> 3;               // 0..127
            int ac4 = idx & 7;                // 0..7 (float4 group)
            int grow = block_row + ar;
            float4 v = make_float4(0.f, 0.f, 0.f, 0.f);
            if (grow < N_NODES)
                v = *(const float4*)(x + (size_t)grow * IN_F + k0 + ac4 * 4);
            As[ac4 * 4 + 0][ar] = v.x;
            As[ac4 * 4 + 1][ar] = v.y;
            As[ac4 * 4 + 2][ar] = v.z;
            As[ac4 * 4 + 3][ar] = v.w;
        }
        // Load B tile (32 k x 128 n), coalesced
#pragma unroll
        for (int l = 0; l < 4; l++) {
            int idx = tid + l * 256;          // 0..1023
            int br  = idx >> 5;               // 0..31
            int bc4 = idx & 31;               // 0..31
            *(float4*)(&Bs[br][bc4 * 4]) =
                *(const float4*)(W + (size_t)(k0 + br) * OUT_F + bc4 * 4);
        }
        __syncthreads();

#pragma unroll
        for (int kk = 0; kk < 32; kk++) {
            float a[8], b[8];
            *(float4*)(a)     = *(const float4*)(&As[kk][ty * 8]);
            *(float4*)(a + 4) = *(const float4*)(&As[kk][ty * 8 + 4]);
            *(float4*)(b)     = *(const float4*)(&Bs[kk][tx * 8]);
            *(float4*)(b + 4) = *(const float4*)(&Bs[kk][tx * 8 + 4]);
#pragma unroll
            for (int i = 0; i < 8; i++)
#pragma unroll
                for (int j = 0; j < 8; j++)
                    acc[i][j] = fmaf(a[i], b[j], acc[i][j]);
        }
        __syncthreads();
    }

    // Epilogue: add bias, store
    float bv[8];
    *(float4*)(bv)     = *(const float4*)(bias + tx * 8);
    *(float4*)(bv + 4) = *(const float4*)(bias + tx * 8 + 4);
#pragma unroll
    for (int i = 0; i < 8; i++) {
        int grow = block_row + ty * 8 + i;
        if (grow < N_NODES) {
            float4 o0, o1;
            o0.x = acc[i][0] + bv[0]; o0.y = acc[i][1] + bv[1];
            o0.z = acc[i][2] + bv[2]; o0.w = acc[i][3] + bv[3];
            o1.x = acc[i][4] + bv[4]; o1.y = acc[i][5] + bv[5];
            o1.z = acc[i][6] + bv[6]; o1.w = acc[i][7] + bv[7];
            float* hp = h + (size_t)grow * OUT_F + tx * 8;
            *(float4*)(hp)     = o0;
            *(float4*)(hp + 4) = o1;
        }
    }
}

// ---------------------------------------------------------------------------
// Zero-init output (harness poisons d_out with 0xAA)
// ---------------------------------------------------------------------------
__global__ void zero_kernel(float4* __restrict__ out, int n4)
{
    int i = blockIdx.x * blockDim.x + threadIdx.x;
    int stride = gridDim.x * blockDim.x;
    float4 z = make_float4(0.f, 0.f, 0.f, 0.f);
    for (; i < n4; i += stride) out[i] = z;
}

// ---------------------------------------------------------------------------
// Scatter: out[row[e]] += val[e] * h[col[e]]
// One warp per edge: lane covers one float4 of the 128-float row.
// Vector reduction (red.global.add.v4.f32) — no return, 1/4 the atomic ops.
// ---------------------------------------------------------------------------
__global__ __launch_bounds__(256) void scatter_kernel(
    const int*   __restrict__ rows,
    const int*   __restrict__ cols,
    const float* __restrict__ vals,
    const float* __restrict__ h,
    float*       __restrict__ out,
    int E)
{
    const int lane = threadIdx.x & 31;
    int w = (blockIdx.x * blockDim.x + threadIdx.x) >> 5;
    const int nwarps = (gridDim.x * blockDim.x) >> 5;

    for (int e = w; e < E; e += nwarps) {
        int   r = rows[e];   // all lanes same address -> broadcast
        int   c = cols[e];
        float v = vals[e];

        float4 m = *(const float4*)(h + (size_t)c * OUT_F + lane * 4);
        m.x *= v; m.y *= v; m.z *= v; m.w *= v;

        float* op = out + (size_t)r * OUT_F + lane * 4;
        asm volatile("red.global.add.v4.f32 [%0], {%1, %2, %3, %4};"
                     :: "l"(op), "f"(m.x), "f"(m.y), "f"(m.z), "f"(m.w)
                     : "memory");
    }
}

// ---------------------------------------------------------------------------
extern "C" void kernel_launch(void* const* d_in, const int* in_sizes, int n_in,
                              void* d_out, int out_size)
{
    const float* x    = (const float*)d_in[0];
    const int*   erow = (const int*)  d_in[1];
    const int*   ecol = (const int*)  d_in[2];
    const float* eval = (const float*)d_in[3];
    const float* W    = (const float*)d_in[4];
    const float* bias = (const float*)d_in[5];
    float* out = (float*)d_out;

    float* h;
    cudaGetSymbolAddress((void**)&h, g_h);

    // GEMM: 782 blocks of 128 rows
    gemm_kernel<<<(N_NODES + 127) / 128, 256>>>(x, W, bias, h);

    // Zero out (poisoned by harness)
    int n4 = N_NODES * OUT_F / 4;  // 3.2M float4
    zero_kernel<<<1184, 256>>>((float4*)out, n4);

    // Scatter with vector atomics; grid-stride, ~8 blocks/SM
    scatter_kernel<<<1184, 256>>>(erow, ecol, eval, h, out, N_EDGES);
}

// round 3
// speedup vs baseline: 1.4377x; 1.4377x over previous
#include <cuda_runtime.h>
#include <cstdint>

#define N_NODES 100000
#define N_EDGES 1600000
#define IN_F 256
#define OUT_F 128

// Scratch for h = x @ W + b  (51.2 MB). __device__ global: allowed (no cudaMalloc).
__device__ float g_h[(size_t)N_NODES * OUT_F];

// ---------------------------------------------------------------------------
// GEMM via tf32 tensor cores: h[M,128] = x[M,256] @ W[256,128] + bias
// BM=128, BN=128, BK=32, 256 threads (8 warps as 4Mx2N), warp tile 32x64,
// mma.sync.m16n8k8.tf32 (2 m-frags x 8 n-frags per warp per k8 step).
// Smem padded: A stride 36, B stride 136 -> bank == lane (conflict-free)
// for every fragment load pattern.
// ---------------------------------------------------------------------------
#define BM 128
#define BN 128
#define BK 32
#define A_STR 36
#define B_STR 136

__device__ __forceinline__ uint32_t f2tf32(float f) {
    uint32_t u;
    asm("cvt.rna.tf32.f32 %0, %1;" : "=r"(u) : "f"(f));
    return u;
}

__global__ __launch_bounds__(256) void gemm_tf32_kernel(
    const float* __restrict__ x,
    const float* __restrict__ W,
    const float* __restrict__ bias,
    float* __restrict__ h)
{
    __shared__ uint32_t As[BM][A_STR];   // 128 x 36 (tf32 bits)
    __shared__ uint32_t Bs[BK][B_STR];   // 32 x 136

    const int tid  = threadIdx.x;
    const int lane = tid & 31;
    const int wid  = tid >> 5;        // 0..7
    const int wm   = wid >> 1;        // 0..3 -> M offset wm*32
    const int wn   = wid & 1;         // 0..1 -> N offset wn*64
    const int block_row = blockIdx.x * BM;

    float acc[2][8][4];
#pragma unroll
    for (int mi = 0; mi < 2; mi++)
#pragma unroll
        for (int ni = 0; ni < 8; ni++)
#pragma unroll
            for (int q = 0; q < 4; q++) acc[mi][ni][q] = 0.0f;

    for (int k0 = 0; k0 < IN_F; k0 += BK) {
        // ---- Load A tile (128 rows x 32 k), cvt to tf32 ----
#pragma unroll
        for (int it = 0; it < 4; it++) {
            int idx = tid + it * 256;          // 0..1023
            int r   = idx >> 3;                // 0..127
            int c4  = idx & 7;                 // float4 group 0..7
            int grow = block_row + r;
            float4 v = make_float4(0.f, 0.f, 0.f, 0.f);
            if (grow < N_NODES)
                v = *(const float4*)(x + (size_t)grow * IN_F + k0 + c4 * 4);
            As[r][c4 * 4 + 0] = f2tf32(v.x);
            As[r][c4 * 4 + 1] = f2tf32(v.y);
            As[r][c4 * 4 + 2] = f2tf32(v.z);
            As[r][c4 * 4 + 3] = f2tf32(v.w);
        }
        // ---- Load B tile (32 k x 128 n), cvt to tf32 ----
#pragma unroll
        for (int it = 0; it < 4; it++) {
            int idx = tid + it * 256;          // 0..1023
            int kr  = idx >> 5;                // 0..31
            int c4  = idx & 31;                // 0..31
            float4 v = *(const float4*)(W + (size_t)(k0 + kr) * OUT_F + c4 * 4);
            Bs[kr][c4 * 4 + 0] = f2tf32(v.x);
            Bs[kr][c4 * 4 + 1] = f2tf32(v.y);
            Bs[kr][c4 * 4 + 2] = f2tf32(v.z);
            Bs[kr][c4 * 4 + 3] = f2tf32(v.w);
        }
        __syncthreads();

#pragma unroll
        for (int ks = 0; ks < BK; ks += 8) {
            uint32_t af[2][4], bf[8][2];
#pragma unroll
            for (int mi = 0; mi < 2; mi++) {
                int r = wm * 32 + mi * 16 + (lane >> 2);
                int c = ks + (lane & 3);
                af[mi][0] = As[r][c];
                af[mi][1] = As[r + 8][c];
                af[mi][2] = As[r][c + 4];
                af[mi][3] = As[r + 8][c + 4];
            }
#pragma unroll
            for (int ni = 0; ni < 8; ni++) {
                int col = wn * 64 + ni * 8 + (lane >> 2);
                bf[ni][0] = Bs[ks + (lane & 3)][col];
                bf[ni][1] = Bs[ks + (lane & 3) + 4][col];
            }
#pragma unroll
            for (int mi = 0; mi < 2; mi++)
#pragma unroll
                for (int ni = 0; ni < 8; ni++) {
                    asm volatile(
                        "mma.sync.aligned.m16n8k8.row.col.f32.tf32.tf32.f32 "
                        "{%0,%1,%2,%3}, {%4,%5,%6,%7}, {%8,%9}, {%0,%1,%2,%3};"
                        : "+f"(acc[mi][ni][0]), "+f"(acc[mi][ni][1]),
                          "+f"(acc[mi][ni][2]), "+f"(acc[mi][ni][3])
                        : "r"(af[mi][0]), "r"(af[mi][1]),
                          "r"(af[mi][2]), "r"(af[mi][3]),
                          "r"(bf[ni][0]), "r"(bf[ni][1]));
                }
        }
        __syncthreads();
    }

    // ---- Epilogue: bias + store (accum layout: c0,c1 at row r, cols 2c,2c+1;
    //      c2,c3 at row r+8) ----
#pragma unroll
    for (int mi = 0; mi < 2; mi++) {
        int r0 = block_row + wm * 32 + mi * 16 + (lane >> 2);
#pragma unroll
        for (int ni = 0; ni < 8; ni++) {
            int col = wn * 64 + ni * 8 + 2 * (lane & 3);
            float b0 = bias[col], b1 = bias[col + 1];
            if (r0 < N_NODES) {
                float2 o = make_float2(acc[mi][ni][0] + b0, acc[mi][ni][1] + b1);
                *(float2*)(h + (size_t)r0 * OUT_F + col) = o;
            }
            if (r0 + 8 < N_NODES) {
                float2 o = make_float2(acc[mi][ni][2] + b0, acc[mi][ni][3] + b1);
                *(float2*)(h + (size_t)(r0 + 8) * OUT_F + col) = o;
            }
        }
    }
}

// ---------------------------------------------------------------------------
// Zero-init output (harness poisons d_out with 0xAA)
// ---------------------------------------------------------------------------
__global__ void zero_kernel(float4* __restrict__ out, int n4)
{
    int i = blockIdx.x * blockDim.x + threadIdx.x;
    int stride = gridDim.x * blockDim.x;
    float4 z = make_float4(0.f, 0.f, 0.f, 0.f);
    for (; i < n4; i += stride) out[i] = z;
}

// ---------------------------------------------------------------------------
// Scatter: out[row[e]] += val[e] * h[col[e]]
// One warp per edge: lane covers one float4 of the 128-float row.
// Vector reduction (red.global.add.v4.f32) — no return, 1/4 the atomic ops.
// ---------------------------------------------------------------------------
__global__ __launch_bounds__(256) void scatter_kernel(
    const int*   __restrict__ rows,
    const int*   __restrict__ cols,
    const float* __restrict__ vals,
    const float* __restrict__ h,
    float*       __restrict__ out,
    int E)
{
    const int lane = threadIdx.x & 31;
    int w = (blockIdx.x * blockDim.x + threadIdx.x) >> 5;
    const int nwarps = (gridDim.x * blockDim.x) >> 5;

    for (int e = w; e < E; e += nwarps) {
        int   r = rows[e];   // all lanes same address -> broadcast
        int   c = cols[e];
        float v = vals[e];

        float4 m = *(const float4*)(h + (size_t)c * OUT_F + lane * 4);
        m.x *= v; m.y *= v; m.z *= v; m.w *= v;

        float* op = out + (size_t)r * OUT_F + lane * 4;
        asm volatile("red.global.add.v4.f32 [%0], {%1, %2, %3, %4};"
                     :: "l"(op), "f"(m.x), "f"(m.y), "f"(m.z), "f"(m.w)
                     : "memory");
    }
}

// ---------------------------------------------------------------------------
extern "C" void kernel_launch(void* const* d_in, const int* in_sizes, int n_in,
                              void* d_out, int out_size)
{
    const float* x    = (const float*)d_in[0];
    const int*   erow = (const int*)  d_in[1];
    const int*   ecol = (const int*)  d_in[2];
    const float* eval = (const float*)d_in[3];
    const float* W    = (const float*)d_in[4];
    const float* bias = (const float*)d_in[5];
    float* out = (float*)d_out;

    float* h;
    cudaGetSymbolAddress((void**)&h, g_h);

    // GEMM on tensor cores: 782 blocks of 128 rows
    gemm_tf32_kernel<<<(N_NODES + BM - 1) / BM, 256>>>(x, W, bias, h);

    // Zero out (poisoned by harness)
    int n4 = N_NODES * OUT_F / 4;  // 3.2M float4
    zero_kernel<<<1184, 256>>>((float4*)out, n4);

    // Scatter with vector atomics; grid-stride, ~8 blocks/SM
    scatter_kernel<<<1184, 256>>>(erow, ecol, eval, h, out, N_EDGES);
}

// round 6
// speedup vs baseline: 1.9810x; 1.3778x over previous
#include <cuda_runtime.h>
#include <cstdint>

#define N_NODES 100000
#define N_EDGES 1600000
#define IN_F 256
#define OUT_F 128

// Device scratch (allocation-free rule: __device__ globals)
__device__ float g_h[(size_t)N_NODES * OUT_F];        // 51.2 MB
__device__ int   g_cnt[N_NODES];                       // histogram
__device__ int   g_off[N_NODES + 1];                   // CSR offsets
__device__ int   g_pos[N_NODES];                       // insertion cursors
__device__ int   g_bsum[128];                          // scan block sums
__device__ int   g_ecol_s[N_EDGES];                    // sorted cols
__device__ float g_eval_s[N_EDGES];                    // sorted vals

// ---------------------------------------------------------------------------
// GEMM via tf32 tensor cores (unchanged from R2): h = x @ W + b
// ---------------------------------------------------------------------------
#define BM 128
#define BK 32
#define A_STR 36
#define B_STR 136

__device__ __forceinline__ uint32_t f2tf32(float f) {
    uint32_t u;
    asm("cvt.rna.tf32.f32 %0, %1;" : "=r"(u) : "f"(f));
    return u;
}

__global__ __launch_bounds__(256) void gemm_tf32_kernel(
    const float* __restrict__ x,
    const float* __restrict__ W,
    const float* __restrict__ bias,
    float* __restrict__ h)
{
    __shared__ uint32_t As[BM][A_STR];
    __shared__ uint32_t Bs[BK][B_STR];

    const int tid  = threadIdx.x;
    const int lane = tid & 31;
    const int wid  = tid >> 5;
    const int wm   = wid >> 1;
    const int wn   = wid & 1;
    const int block_row = blockIdx.x * BM;

    float acc[2][8][4];
#pragma unroll
    for (int mi = 0; mi < 2; mi++)
#pragma unroll
        for (int ni = 0; ni < 8; ni++)
#pragma unroll
            for (int q = 0; q < 4; q++) acc[mi][ni][q] = 0.0f;

    for (int k0 = 0; k0 < IN_F; k0 += BK) {
#pragma unroll
        for (int it = 0; it < 4; it++) {
            int idx = tid + it * 256;
            int r   = idx >> 3;
            int c4  = idx & 7;
            int grow = block_row + r;
            float4 v = make_float4(0.f, 0.f, 0.f, 0.f);
            if (grow < N_NODES)
                v = *(const float4*)(x + (size_t)grow * IN_F + k0 + c4 * 4);
            As[r][c4 * 4 + 0] = f2tf32(v.x);
            As[r][c4 * 4 + 1] = f2tf32(v.y);
            As[r][c4 * 4 + 2] = f2tf32(v.z);
            As[r][c4 * 4 + 3] = f2tf32(v.w);
        }
#pragma unroll
        for (int it = 0; it < 4; it++) {
            int idx = tid + it * 256;
            int kr  = idx >> 5;
            int c4  = idx & 31;
            float4 v = *(const float4*)(W + (size_t)(k0 + kr) * OUT_F + c4 * 4);
            Bs[kr][c4 * 4 + 0] = f2tf32(v.x);
            Bs[kr][c4 * 4 + 1] = f2tf32(v.y);
            Bs[kr][c4 * 4 + 2] = f2tf32(v.z);
            Bs[kr][c4 * 4 + 3] = f2tf32(v.w);
        }
        __syncthreads();

#pragma unroll
        for (int ks = 0; ks < BK; ks += 8) {
            uint32_t af[2][4], bf[8][2];
#pragma unroll
            for (int mi = 0; mi < 2; mi++) {
                int r = wm * 32 + mi * 16 + (lane >> 2);
                int c = ks + (lane & 3);
                af[mi][0] = As[r][c];
                af[mi][1] = As[r + 8][c];
                af[mi][2] = As[r][c + 4];
                af[mi][3] = As[r + 8][c + 4];
            }
#pragma unroll
            for (int ni = 0; ni < 8; ni++) {
                int col = wn * 64 + ni * 8 + (lane >> 2);
                bf[ni][0] = Bs[ks + (lane & 3)][col];
                bf[ni][1] = Bs[ks + (lane & 3) + 4][col];
            }
#pragma unroll
            for (int mi = 0; mi < 2; mi++)
#pragma unroll
                for (int ni = 0; ni < 8; ni++) {
                    asm volatile(
                        "mma.sync.aligned.m16n8k8.row.col.f32.tf32.tf32.f32 "
                        "{%0,%1,%2,%3}, {%4,%5,%6,%7}, {%8,%9}, {%0,%1,%2,%3};"
                        : "+f"(acc[mi][ni][0]), "+f"(acc[mi][ni][1]),
                          "+f"(acc[mi][ni][2]), "+f"(acc[mi][ni][3])
                        : "r"(af[mi][0]), "r"(af[mi][1]),
                          "r"(af[mi][2]), "r"(af[mi][3]),
                          "r"(bf[ni][0]), "r"(bf[ni][1]));
                }
        }
        __syncthreads();
    }

#pragma unroll
    for (int mi = 0; mi < 2; mi++) {
        int r0 = block_row + wm * 32 + mi * 16 + (lane >> 2);
#pragma unroll
        for (int ni = 0; ni < 8; ni++) {
            int col = wn * 64 + ni * 8 + 2 * (lane & 3);
            float b0 = bias[col], b1 = bias[col + 1];
            if (r0 < N_NODES) {
                float2 o = make_float2(acc[mi][ni][0] + b0, acc[mi][ni][1] + b1);
                *(float2*)(h + (size_t)r0 * OUT_F + col) = o;
            }
            if (r0 + 8 < N_NODES) {
                float2 o = make_float2(acc[mi][ni][2] + b0, acc[mi][ni][3] + b1);
                *(float2*)(h + (size_t)(r0 + 8) * OUT_F + col) = o;
            }
        }
    }
}

// ---------------------------------------------------------------------------
// CSR construction: histogram -> scan -> reorder
// ---------------------------------------------------------------------------
__global__ void zero_cnt_kernel(int* __restrict__ cnt, int n)
{
    int i = blockIdx.x * blockDim.x + threadIdx.x;
    int stride = gridDim.x * blockDim.x;
    for (; i < n; i += stride) cnt[i] = 0;
}

__global__ void hist_kernel(const int* __restrict__ rows, int* __restrict__ cnt, int E)
{
    int i = blockIdx.x * blockDim.x + threadIdx.x;
    int stride = gridDim.x * blockDim.x;
    for (; i < E; i += stride) {
        int r = rows[i];
        asm volatile("red.global.add.u32 [%0], %1;"
                     :: "l"(cnt + r), "r"(1) : "memory");
    }
}

// scan1: per-block (1024 elems) local exclusive scan + block sum
__global__ __launch_bounds__(256) void scan1_kernel(
    const int* __restrict__ cnt, int* __restrict__ pre,
    int* __restrict__ bsum, int n)
{
    __shared__ int s[256];
    const int tid = threadIdx.x;
    int base = blockIdx.x * 1024 + tid * 4;
    int v[4]; int sum = 0;
#pragma unroll
    for (int i = 0; i < 4; i++) {
        v[i] = (base + i < n) ? cnt[base + i] : 0;
        sum += v[i];
    }
    s[tid] = sum;
    __syncthreads();
#pragma unroll
    for (int off = 1; off < 256; off <<= 1) {
        int t = (tid >= off) ? s[tid - off] : 0;
        __syncthreads();
        s[tid] += t;
        __syncthreads();
    }
    int running = (tid == 0) ? 0 : s[tid - 1];
#pragma unroll
    for (int i = 0; i < 4; i++) {
        if (base + i < n) pre[base + i] = running;
        running += v[i];
    }
    if (tid == 255) bsum[blockIdx.x] = s[255];
}

// scan2: single block, exclusive scan of block sums (nb <= 128)
__global__ __launch_bounds__(128) void scan2_kernel(int* __restrict__ bsum, int nb)
{
    __shared__ int s[128];
    const int tid = threadIdx.x;
    int v = (tid < nb) ? bsum[tid] : 0;
    s[tid] = v;
    __syncthreads();
#pragma unroll
    for (int off = 1; off < 128; off <<= 1) {
        int t = (tid >= off) ? s[tid - off] : 0;
        __syncthreads();
        s[tid] += t;
        __syncthreads();
    }
    if (tid < nb) bsum[tid] = (tid == 0) ? 0 : s[tid - 1];
}

// scan3: add block offsets, produce final CSR offsets + cursor copy
__global__ void scan3_kernel(int* __restrict__ off, int* __restrict__ pos,
                             const int* __restrict__ bsum, int n, int E)
{
    int i = blockIdx.x * blockDim.x + threadIdx.x;
    int stride = gridDim.x * blockDim.x;
    for (; i < n; i += stride) {
        int o = off[i] + bsum[i >> 10];
        off[i] = o;
        pos[i] = o;
    }
    if (blockIdx.x == 0 && threadIdx.x == 0) off[n] = E;
}

__global__ void reorder_kernel(
    const int*   __restrict__ rows,
    const int*   __restrict__ cols,
    const float* __restrict__ vals,
    int*         __restrict__ pos,
    int*         __restrict__ ecol_s,
    float*       __restrict__ eval_s,
    int E)
{
    int i = blockIdx.x * blockDim.x + threadIdx.x;
    int stride = gridDim.x * blockDim.x;
    for (; i < E; i += stride) {
        int   r = rows[i];
        int   c = cols[i];
        float v = vals[i];
        int p = atomicAdd(pos + r, 1);
        ecol_s[p] = c;
        eval_s[p] = v;
    }
}

// ---------------------------------------------------------------------------
// Aggregate: one warp per destination node. Register accumulation, single
// plain store — no atomics, no zero-init pass.
// ---------------------------------------------------------------------------
__global__ __launch_bounds__(256) void aggregate_kernel(
    const int*   __restrict__ off,
    const int*   __restrict__ ecol_s,
    const float* __restrict__ eval_s,
    const float* __restrict__ h,
    float*       __restrict__ out)
{
    const int lane = threadIdx.x & 31;
    const int node = blockIdx.x * 8 + (threadIdx.x >> 5);
    if (node >= N_NODES) return;

    int s = off[node];
    int e = off[node + 1];

    float4 acc = make_float4(0.f, 0.f, 0.f, 0.f);
    int i = s;
    // unrolled by 2 for memory-level parallelism
    for (; i + 1 < e; i += 2) {
        int   c0 = ecol_s[i],     c1 = ecol_s[i + 1];
        float v0 = eval_s[i],     v1 = eval_s[i + 1];
        float4 m0 = *(const float4*)(h + (size_t)c0 * OUT_F + lane * 4);
        float4 m1 = *(const float4*)(h + (size_t)c1 * OUT_F + lane * 4);
        acc.x += v0 * m0.x + v1 * m1.x;
        acc.y += v0 * m0.y + v1 * m1.y;
        acc.z += v0 * m0.z + v1 * m1.z;
        acc.w += v0 * m0.w + v1 * m1.w;
    }
    if (i < e) {
        int   c = ecol_s[i];
        float v = eval_s[i];
        float4 m = *(const float4*)(h + (size_t)c * OUT_F + lane * 4);
        acc.x += v * m.x; acc.y += v * m.y;
        acc.z += v * m.z; acc.w += v * m.w;
    }

    *(float4*)(out + (size_t)node * OUT_F + lane * 4) = acc;
}

// ---------------------------------------------------------------------------
extern "C" void kernel_launch(void* const* d_in, const int* in_sizes, int n_in,
                              void* d_out, int out_size)
{
    const float* x    = (const float*)d_in[0];
    const int*   erow = (const int*)  d_in[1];
    const int*   ecol = (const int*)  d_in[2];
    const float* eval = (const float*)d_in[3];
    const float* W    = (const float*)d_in[4];
    const float* bias = (const float*)d_in[5];
    float* out = (float*)d_out;

    float* h;     cudaGetSymbolAddress((void**)&h, g_h);
    int*   cnt;   cudaGetSymbolAddress((void**)&cnt, g_cnt);
    int*   off;   cudaGetSymbolAddress((void**)&off, g_off);
    int*   pos;   cudaGetSymbolAddress((void**)&pos, g_pos);
    int*   bsum;  cudaGetSymbolAddress((void**)&bsum, g_bsum);
    int*   ecs;   cudaGetSymbolAddress((void**)&ecs, g_ecol_s);
    float* evs;   cudaGetSymbolAddress((void**)&evs, g_eval_s);

    const int NBLK_SCAN = (N_NODES + 1023) / 1024;  // 98

    // GEMM on tensor cores
    gemm_tf32_kernel<<<(N_NODES + BM - 1) / BM, 256>>>(x, W, bias, h);

    // CSR build (independent of GEMM result)
    zero_cnt_kernel<<<98, 256>>>(cnt, N_NODES);
    hist_kernel<<<1184, 256>>>(erow, cnt, N_EDGES);
    scan1_kernel<<<NBLK_SCAN, 256>>>(cnt, off, bsum, N_NODES);
    scan2_kernel<<<1, 128>>>(bsum, NBLK_SCAN);
    scan3_kernel<<<98, 256>>>(off, pos, bsum, N_NODES, N_EDGES);
    reorder_kernel<<<1184, 256>>>(erow, ecol, eval, pos, ecs, evs, N_EDGES);

    // Per-node aggregation (no atomics)
    aggregate_kernel<<<(N_NODES + 7) / 8, 256>>>(off, ecs, evs, h, out);
}

// round 7
// speedup vs baseline: 2.2772x; 1.1495x over previous
#include <cuda_runtime.h>
#include <cuda_fp16.h>
#include <cstdint>

#define N_NODES 100000
#define N_EDGES 1600000
#define IN_F 256
#define OUT_F 128

// Device scratch (allocation-free rule: __device__ globals)
__device__ __half g_h[(size_t)N_NODES * OUT_F];       // 25.6 MB (fp16 h)
__device__ int    g_cnt[N_NODES];                      // histogram
__device__ int    g_off[N_NODES + 1];                  // CSR offsets
__device__ int    g_pos[N_NODES];                      // insertion cursors
__device__ int    g_bsum[128];                         // scan block sums
__device__ int2   g_ep[N_EDGES];                       // packed (col, val_bits)

// ---------------------------------------------------------------------------
// GEMM via tf32 tensor cores: h(fp16) = x @ W + b
// ---------------------------------------------------------------------------
#define BM 128
#define BK 32
#define A_STR 36
#define B_STR 136

__device__ __forceinline__ uint32_t f2tf32(float f) {
    uint32_t u;
    asm("cvt.rna.tf32.f32 %0, %1;" : "=r"(u) : "f"(f));
    return u;
}

__global__ __launch_bounds__(256) void gemm_tf32_kernel(
    const float* __restrict__ x,
    const float* __restrict__ W,
    const float* __restrict__ bias,
    __half* __restrict__ h)
{
    __shared__ uint32_t As[BM][A_STR];
    __shared__ uint32_t Bs[BK][B_STR];

    const int tid  = threadIdx.x;
    const int lane = tid & 31;
    const int wid  = tid >> 5;
    const int wm   = wid >> 1;
    const int wn   = wid & 1;
    const int block_row = blockIdx.x * BM;

    float acc[2][8][4];
#pragma unroll
    for (int mi = 0; mi < 2; mi++)
#pragma unroll
        for (int ni = 0; ni < 8; ni++)
#pragma unroll
            for (int q = 0; q < 4; q++) acc[mi][ni][q] = 0.0f;

    for (int k0 = 0; k0 < IN_F; k0 += BK) {
#pragma unroll
        for (int it = 0; it < 4; it++) {
            int idx = tid + it * 256;
            int r   = idx >> 3;
            int c4  = idx & 7;
            int grow = block_row + r;
            float4 v = make_float4(0.f, 0.f, 0.f, 0.f);
            if (grow < N_NODES)
                v = *(const float4*)(x + (size_t)grow * IN_F + k0 + c4 * 4);
            As[r][c4 * 4 + 0] = f2tf32(v.x);
            As[r][c4 * 4 + 1] = f2tf32(v.y);
            As[r][c4 * 4 + 2] = f2tf32(v.z);
            As[r][c4 * 4 + 3] = f2tf32(v.w);
        }
#pragma unroll
        for (int it = 0; it < 4; it++) {
            int idx = tid + it * 256;
            int kr  = idx >> 5;
            int c4  = idx & 31;
            float4 v = *(const float4*)(W + (size_t)(k0 + kr) * OUT_F + c4 * 4);
            Bs[kr][c4 * 4 + 0] = f2tf32(v.x);
            Bs[kr][c4 * 4 + 1] = f2tf32(v.y);
            Bs[kr][c4 * 4 + 2] = f2tf32(v.z);
            Bs[kr][c4 * 4 + 3] = f2tf32(v.w);
        }
        __syncthreads();

#pragma unroll
        for (int ks = 0; ks < BK; ks += 8) {
            uint32_t af[2][4], bf[8][2];
#pragma unroll
            for (int mi = 0; mi < 2; mi++) {
                int r = wm * 32 + mi * 16 + (lane >> 2);
                int c = ks + (lane & 3);
                af[mi][0] = As[r][c];
                af[mi][1] = As[r + 8][c];
                af[mi][2] = As[r][c + 4];
                af[mi][3] = As[r + 8][c + 4];
            }
#pragma unroll
            for (int ni = 0; ni < 8; ni++) {
                int col = wn * 64 + ni * 8 + (lane >> 2);
                bf[ni][0] = Bs[ks + (lane & 3)][col];
                bf[ni][1] = Bs[ks + (lane & 3) + 4][col];
            }
#pragma unroll
            for (int mi = 0; mi < 2; mi++)
#pragma unroll
                for (int ni = 0; ni < 8; ni++) {
                    asm volatile(
                        "mma.sync.aligned.m16n8k8.row.col.f32.tf32.tf32.f32 "
                        "{%0,%1,%2,%3}, {%4,%5,%6,%7}, {%8,%9}, {%0,%1,%2,%3};"
                        : "+f"(acc[mi][ni][0]), "+f"(acc[mi][ni][1]),
                          "+f"(acc[mi][ni][2]), "+f"(acc[mi][ni][3])
                        : "r"(af[mi][0]), "r"(af[mi][1]),
                          "r"(af[mi][2]), "r"(af[mi][3]),
                          "r"(bf[ni][0]), "r"(bf[ni][1]));
                }
        }
        __syncthreads();
    }

    // Epilogue: bias + fp16 store (pairs c0,c1 at row r; c2,c3 at row r+8)
#pragma unroll
    for (int mi = 0; mi < 2; mi++) {
        int r0 = block_row + wm * 32 + mi * 16 + (lane >> 2);
#pragma unroll
        for (int ni = 0; ni < 8; ni++) {
            int col = wn * 64 + ni * 8 + 2 * (lane & 3);
            float b0 = bias[col], b1 = bias[col + 1];
            if (r0 < N_NODES) {
                __half2 p = __floats2half2_rn(acc[mi][ni][0] + b0,
                                              acc[mi][ni][1] + b1);
                *(__half2*)(h + (size_t)r0 * OUT_F + col) = p;
            }
            if (r0 + 8 < N_NODES) {
                __half2 p = __floats2half2_rn(acc[mi][ni][2] + b0,
                                              acc[mi][ni][3] + b1);
                *(__half2*)(h + (size_t)(r0 + 8) * OUT_F + col) = p;
            }
        }
    }
}

// ---------------------------------------------------------------------------
// CSR construction: histogram -> scan -> reorder (packed pairs)
// ---------------------------------------------------------------------------
__global__ void zero_cnt_kernel(int* __restrict__ cnt, int n)
{
    int i = blockIdx.x * blockDim.x + threadIdx.x;
    int stride = gridDim.x * blockDim.x;
    for (; i < n; i += stride) cnt[i] = 0;
}

__global__ void hist_kernel(const int* __restrict__ rows, int* __restrict__ cnt, int E)
{
    int i = blockIdx.x * blockDim.x + threadIdx.x;
    int stride = gridDim.x * blockDim.x;
    for (; i < E; i += stride) {
        int r = rows[i];
        asm volatile("red.global.add.u32 [%0], %1;"
                     :: "l"(cnt + r), "r"(1) : "memory");
    }
}

__global__ __launch_bounds__(256) void scan1_kernel(
    const int* __restrict__ cnt, int* __restrict__ pre,
    int* __restrict__ bsum, int n)
{
    __shared__ int s[256];
    const int tid = threadIdx.x;
    int base = blockIdx.x * 1024 + tid * 4;
    int v[4]; int sum = 0;
#pragma unroll
    for (int i = 0; i < 4; i++) {
        v[i] = (base + i < n) ? cnt[base + i] : 0;
        sum += v[i];
    }
    s[tid] = sum;
    __syncthreads();
#pragma unroll
    for (int off = 1; off < 256; off <<= 1) {
        int t = (tid >= off) ? s[tid - off] : 0;
        __syncthreads();
        s[tid] += t;
        __syncthreads();
    }
    int running = (tid == 0) ? 0 : s[tid - 1];
#pragma unroll
    for (int i = 0; i < 4; i++) {
        if (base + i < n) pre[base + i] = running;
        running += v[i];
    }
    if (tid == 255) bsum[blockIdx.x] = s[255];
}

__global__ __launch_bounds__(128) void scan2_kernel(int* __restrict__ bsum, int nb)
{
    __shared__ int s[128];
    const int tid = threadIdx.x;
    int v = (tid < nb) ? bsum[tid] : 0;
    s[tid] = v;
    __syncthreads();
#pragma unroll
    for (int off = 1; off < 128; off <<= 1) {
        int t = (tid >= off) ? s[tid - off] : 0;
        __syncthreads();
        s[tid] += t;
        __syncthreads();
    }
    if (tid < nb) bsum[tid] = (tid == 0) ? 0 : s[tid - 1];
}

__global__ void scan3_kernel(int* __restrict__ off, int* __restrict__ pos,
                             const int* __restrict__ bsum, int n, int E)
{
    int i = blockIdx.x * blockDim.x + threadIdx.x;
    int stride = gridDim.x * blockDim.x;
    for (; i < n; i += stride) {
        int o = off[i] + bsum[i >> 10];
        off[i] = o;
        pos[i] = o;
    }
    if (blockIdx.x == 0 && threadIdx.x == 0) off[n] = E;
}

__global__ void reorder_kernel(
    const int*   __restrict__ rows,
    const int*   __restrict__ cols,
    const float* __restrict__ vals,
    int*         __restrict__ pos,
    int2*        __restrict__ ep,
    int E)
{
    int i = blockIdx.x * blockDim.x + threadIdx.x;
    int stride = gridDim.x * blockDim.x;
    for (; i < E; i += stride) {
        int   c = cols[i];
        float v = vals[i];
        int   r = rows[i];
        int p = atomicAdd(pos + r, 1);
        ep[p] = make_int2(c, __float_as_int(v));   // single STG.64
    }
}

// ---------------------------------------------------------------------------
// Aggregate: one warp per destination node. fp16 h gather (8B/lane),
// fp32 accumulation, single float4 store. No atomics.
// ---------------------------------------------------------------------------
__global__ __launch_bounds__(256) void aggregate_kernel(
    const int*    __restrict__ off,
    const int2*   __restrict__ ep,
    const __half* __restrict__ h,
    float*        __restrict__ out)
{
    const int lane = threadIdx.x & 31;
    const int node = blockIdx.x * 8 + (threadIdx.x >> 5);
    if (node >= N_NODES) return;

    int s = off[node];
    int e = off[node + 1];

    float4 acc = make_float4(0.f, 0.f, 0.f, 0.f);
    int i = s;

#define GATHER_ONE(CC, VV)                                                   \
    {                                                                        \
        const uint2 raw = *(const uint2*)(h + (size_t)(CC) * OUT_F + lane * 4); \
        float2 lo = __half22float2(*(const __half2*)&raw.x);                 \
        float2 hi = __half22float2(*(const __half2*)&raw.y);                 \
        acc.x = fmaf((VV), lo.x, acc.x);                                     \
        acc.y = fmaf((VV), lo.y, acc.y);                                     \
        acc.z = fmaf((VV), hi.x, acc.z);                                     \
        acc.w = fmaf((VV), hi.y, acc.w);                                     \
    }

    // unroll by 4 for memory-level parallelism (mean degree = 16)
    for (; i + 3 < e; i += 4) {
        int2 p0 = ep[i],     p1 = ep[i + 1];
        int2 p2 = ep[i + 2], p3 = ep[i + 3];
        GATHER_ONE(p0.x, __int_as_float(p0.y));
        GATHER_ONE(p1.x, __int_as_float(p1.y));
        GATHER_ONE(p2.x, __int_as_float(p2.y));
        GATHER_ONE(p3.x, __int_as_float(p3.y));
    }
    for (; i < e; i++) {
        int2 p = ep[i];
        GATHER_ONE(p.x, __int_as_float(p.y));
    }
#undef GATHER_ONE

    *(float4*)(out + (size_t)node * OUT_F + lane * 4) = acc;
}

// ---------------------------------------------------------------------------
extern "C" void kernel_launch(void* const* d_in, const int* in_sizes, int n_in,
                              void* d_out, int out_size)
{
    const float* x    = (const float*)d_in[0];
    const int*   erow = (const int*)  d_in[1];
    const int*   ecol = (const int*)  d_in[2];
    const float* eval = (const float*)d_in[3];
    const float* W    = (const float*)d_in[4];
    const float* bias = (const float*)d_in[5];
    float* out = (float*)d_out;

    __half* h;    cudaGetSymbolAddress((void**)&h, g_h);
    int*    cnt;  cudaGetSymbolAddress((void**)&cnt, g_cnt);
    int*    off;  cudaGetSymbolAddress((void**)&off, g_off);
    int*    pos;  cudaGetSymbolAddress((void**)&pos, g_pos);
    int*    bsum; cudaGetSymbolAddress((void**)&bsum, g_bsum);
    int2*   ep;   cudaGetSymbolAddress((void**)&ep, g_ep);

    const int NBLK_SCAN = (N_NODES + 1023) / 1024;  // 98

    // GEMM on tensor cores (fp16 h output)
    gemm_tf32_kernel<<<(N_NODES + BM - 1) / BM, 256>>>(x, W, bias, h);

    // CSR build (independent of GEMM result)
    zero_cnt_kernel<<<98, 256>>>(cnt, N_NODES);
    hist_kernel<<<1184, 256>>>(erow, cnt, N_EDGES);
    scan1_kernel<<<NBLK_SCAN, 256>>>(cnt, off, bsum, N_NODES);
    scan2_kernel<<<1, 128>>>(bsum, NBLK_SCAN);
    scan3_kernel<<<98, 256>>>(off, pos, bsum, N_NODES, N_EDGES);
    reorder_kernel<<<1184, 256>>>(erow, ecol, eval, pos, ep, N_EDGES);

    // Per-node aggregation (no atomics)
    aggregate_kernel<<<(N_NODES + 7) / 8, 256>>>(off, ep, h, out);
}